// round 6
// baseline (speedup 1.0000x reference)
#include <cuda_runtime.h>
#include <cuda_fp16.h>
#include <cstdint>

// Fixed problem shape: B=4, S=2048 -> M=8192, K=IN=4096, N=OUT=4096, group=32
#define IN_MAX  4096
#define OUT_MAX 4096
#define M_MAX   8192

// Static device scratch (allocation-free per harness rules)
__device__ __half g_X[(size_t)M_MAX * IN_MAX];     // x in fp16, [M][K]
__device__ __half g_WT[(size_t)OUT_MAX * IN_MAX];  // dequantized W^T, [N][K] K-major

// ============================================================================
// PTX helpers (sm_80-class, valid on plain sm_103 target)
// ============================================================================
__device__ __forceinline__ uint32_t smem_to_u32(const void* p) {
    uint32_t a;
    asm("{ .reg .u64 t; cvta.to.shared.u64 t, %1; cvt.u32.u64 %0, t; }" : "=r"(a) : "l"(p));
    return a;
}
__device__ __forceinline__ void cp_async16(uint32_t dst, const void* src) {
    asm volatile("cp.async.cg.shared.global [%0], [%1], 16;" :: "r"(dst), "l"(src));
}
__device__ __forceinline__ void cp_async_commit() {
    asm volatile("cp.async.commit_group;" ::: "memory");
}
template <int N>
__device__ __forceinline__ void cp_async_wait() {
    asm volatile("cp.async.wait_group %0;" :: "n"(N) : "memory");
}
__device__ __forceinline__ void ldsm4(uint32_t (&r)[4], uint32_t addr) {
    asm volatile("ldmatrix.sync.aligned.m8n8.x4.shared.b16 {%0,%1,%2,%3}, [%4];"
                 : "=r"(r[0]), "=r"(r[1]), "=r"(r[2]), "=r"(r[3]) : "r"(addr));
}
__device__ __forceinline__ void mma16816(float (&c)[4],
                                         uint32_t a0, uint32_t a1, uint32_t a2, uint32_t a3,
                                         uint32_t b0, uint32_t b1) {
    asm volatile("mma.sync.aligned.m16n8k16.row.col.f32.f16.f16.f32 "
                 "{%0,%1,%2,%3}, {%4,%5,%6,%7}, {%8,%9}, {%0,%1,%2,%3};"
                 : "+f"(c[0]), "+f"(c[1]), "+f"(c[2]), "+f"(c[3])
                 : "r"(a0), "r"(a1), "r"(a2), "r"(a3), "r"(b0), "r"(b1));
}

// ============================================================================
// Fused prep kernel: block-range dispatch
//   blocks [0, convBlocks):          x fp32 -> fp16
//   blocks [convBlocks, ...):        dequant 4-bit -> fp16 W^T [N][K]
// ============================================================================
__global__ void prep_kernel(const float* __restrict__ x, int n4,
                            const int* __restrict__ qweight,
                            const int* __restrict__ qzeros,
                            const int* __restrict__ qscales,
                            const float* __restrict__ qscales_zeros,
                            const float* __restrict__ qscales_scales,
                            const int* __restrict__ g_idx,
                            int K, int N, int convBlocks) {
    if ((int)blockIdx.x < convBlocks) {
        int i = blockIdx.x * blockDim.x + threadIdx.x;
        if (i < n4) {
            float4 v = reinterpret_cast<const float4*>(x)[i];
            __half2 a = __floats2half2_rn(v.x, v.y);
            __half2 b = __floats2half2_rn(v.z, v.w);
            __half2* o = reinterpret_cast<__half2*>(g_X) + 2 * (size_t)i;
            o[0] = a;
            o[1] = b;
        }
    } else {
        int idx = (blockIdx.x - convBlocks) * blockDim.x + threadIdx.x;
        int P = K >> 3;
        if (idx >= P * N) return;
        int p = idx / N;
        int j = idx - p * N;

        // 8 consecutive K rows (p*8..p*8+7) lie in one group (8 | 32)
        int g = g_idx[p * 8];
        int z = (int)(((unsigned)qzeros[g * (N >> 3) + (j >> 3)] >> ((j & 7) * 4)) & 15u) + 1;
        float sc = ((float)qscales[(size_t)g * N + j] - qscales_zeros[g]) * qscales_scales[g];

        unsigned w = (unsigned)qweight[idx];
        __half h[8];
#pragma unroll
        for (int r = 0; r < 8; r++) {
            int wn = (int)((w >> (4 * r)) & 15u);
            h[r] = __float2half_rn((float)(wn - z) * sc);
        }
        *reinterpret_cast<int4*>(&g_WT[(size_t)j * K + p * 8]) = *reinterpret_cast<int4*>(h);
    }
}

// ============================================================================
// GEMM: raw mma.sync.m16n8k16 + ldmatrix, hand-interleaved register pipeline
//   C[M][N] = g_X[M][K] * g_WT[N][K]^T,  fp16 in / fp32 accum
// CTA tile 128x256x64, 8 warps (2x4), warp tile 64x64,
// 4-stage cp.async pipeline (~221KB smem), 144B row stride (conflict-free).
// ============================================================================
#define BM 128
#define BN 256
#define BK 64
#define STAGES 4
#define LDA (BK + 8)          // 72 halves = 144 bytes
#define LDB (BK + 8)

static constexpr int A_ST = BM * LDA * 2;          // 18432 B per stage
static constexpr int B_ST = BN * LDB * 2;          // 36864 B per stage
static constexpr int OFF_B = STAGES * A_ST;        // 73728
static constexpr int SMEM_DYN = OFF_B + STAGES * B_ST + 16;  // ~221KB

__device__ __forceinline__ void load_stage(uint32_t sbase, int stage,
                                           const __half* Abase, const __half* Bbase,
                                           int k0, int K, int tid, bool active) {
    if (active) {
        uint32_t aoff = sbase + stage * A_ST;
        uint32_t boff = sbase + OFF_B + stage * B_ST;
#pragma unroll
        for (int c = 0; c < 4; c++) {
            int i = tid + c * 256;
            int row = i >> 3;
            int cc = i & 7;
            cp_async16(aoff + row * (LDA * 2) + cc * 16,
                       (const char*)(Abase + (size_t)row * K + k0) + cc * 16);
        }
#pragma unroll
        for (int c = 0; c < 8; c++) {
            int i = tid + c * 256;
            int row = i >> 3;
            int cc = i & 7;
            cp_async16(boff + row * (LDB * 2) + cc * 16,
                       (const char*)(Bbase + (size_t)row * K + k0) + cc * 16);
        }
    }
    cp_async_commit();
}

__global__ void __launch_bounds__(256, 1)
gemm_kernel(float* __restrict__ C, int M, int N, int K) {
    extern __shared__ char dsm[];
    uint32_t sbase = smem_to_u32(dsm);

    int tid  = threadIdx.x;
    int lane = tid & 31;
    int warp = tid >> 5;
    int wm   = warp & 1;      // 0..1 -> 64-row slab
    int wn   = warp >> 1;     // 0..3 -> 64-col slab

    int bm = blockIdx.y * BM;
    int bn = blockIdx.x * BN;

    const __half* Abase = &g_X[(size_t)bm * K];
    const __half* Bbase = &g_WT[(size_t)bn * K];

    // ldmatrix byte offsets (within a stage) for this lane:
    //   addr = stage_base + ((tile_row0 + (lane&15)) * LD)*2 + (lane>>4)*16 + kk*2
    uint32_t aoff[4], boff[4];
#pragma unroll
    for (int mi = 0; mi < 4; mi++)
        aoff[mi] = (uint32_t)(wm * 64 + mi * 16 + (lane & 15)) * (LDA * 2) + (lane >> 4) * 16;
#pragma unroll
    for (int nb = 0; nb < 4; nb++)
        boff[nb] = (uint32_t)(wn * 64 + nb * 16 + (lane & 15)) * (LDB * 2) + (lane >> 4) * 16;

    float acc[4][8][4];
#pragma unroll
    for (int mi = 0; mi < 4; mi++)
#pragma unroll
        for (int nj = 0; nj < 8; nj++)
#pragma unroll
            for (int q = 0; q < 4; q++)
                acc[mi][nj][q] = 0.0f;

    int KT = K / BK;  // 64

#pragma unroll
    for (int s = 0; s < STAGES - 1; s++)
        load_stage(sbase, s, Abase, Bbase, s * BK, K, tid, true);

    uint32_t RA[2][4][4];   // [buf][m-tile][4 regs]
    uint32_t RB[2][4][4];   // [buf][n16-tile][4 regs] (two n8 frags per tile)

    for (int kt = 0; kt < KT; kt++) {
        int st = kt % STAGES;
        cp_async_wait<STAGES - 2>();
        __syncthreads();

        load_stage(sbase, (kt + STAGES - 1) % STAGES, Abase, Bbase,
                   (kt + STAGES - 1) * BK, K, tid, (kt + STAGES - 1) < KT);

        uint32_t As = sbase + st * A_ST;
        uint32_t Bs = sbase + OFF_B + st * B_ST;

        // kstep 0 fragments
#pragma unroll
        for (int mi = 0; mi < 4; mi++) ldsm4(RA[0][mi], As + aoff[mi]);
#pragma unroll
        for (int nb = 0; nb < 4; nb++) ldsm4(RB[0][nb], Bs + boff[nb]);

#pragma unroll
        for (int kk = 0; kk < BK / 16; kk++) {
            int cur = kk & 1;
            int nxt = cur ^ 1;
            // Prefetch next kstep fragments (interleaved with mma issue below)
            if (kk < BK / 16 - 1) {
                uint32_t ko = (uint32_t)(kk + 1) * 32;   // 16 halves = 32 bytes
#pragma unroll
                for (int mi = 0; mi < 4; mi++) ldsm4(RA[nxt][mi], As + aoff[mi] + ko);
#pragma unroll
                for (int nb = 0; nb < 4; nb++) ldsm4(RB[nxt][nb], Bs + boff[nb] + ko);
            }
            // 32 mma for this kstep
#pragma unroll
            for (int mi = 0; mi < 4; mi++) {
#pragma unroll
                for (int nj = 0; nj < 8; nj++) {
                    int nb = nj >> 1;
                    int h  = nj & 1;
                    mma16816(acc[mi][nj],
                             RA[cur][mi][0], RA[cur][mi][1], RA[cur][mi][2], RA[cur][mi][3],
                             RB[cur][nb][h], RB[cur][nb][2 + h]);
                }
            }
        }
    }

    // Epilogue: per-thread float2 stores
    //   c0,c1: (row = t>>2, cols 2(t&3), +1); c2,c3: row+8
    int r0 = bm + wm * 64 + (lane >> 2);
    int c0 = bn + wn * 64 + 2 * (lane & 3);
#pragma unroll
    for (int mi = 0; mi < 4; mi++) {
#pragma unroll
        for (int nj = 0; nj < 8; nj++) {
            float* p0 = &C[(size_t)(r0 + mi * 16) * N + c0 + nj * 8];
            float* p1 = &C[(size_t)(r0 + mi * 16 + 8) * N + c0 + nj * 8];
            *reinterpret_cast<float2*>(p0) = make_float2(acc[mi][nj][0], acc[mi][nj][1]);
            *reinterpret_cast<float2*>(p1) = make_float2(acc[mi][nj][2], acc[mi][nj][3]);
        }
    }
}

// ============================================================================
// Launch
// ============================================================================
extern "C" void kernel_launch(void* const* d_in, const int* in_sizes, int n_in,
                              void* d_out, int out_size) {
    const float* x   = (const float*)d_in[0];
    const int*   qw  = (const int*)d_in[1];
    const int*   qz  = (const int*)d_in[2];
    const int*   qs  = (const int*)d_in[3];
    const float* qsz = (const float*)d_in[4];
    const float* qss = (const float*)d_in[5];
    const int*   gix = (const int*)d_in[6];

    int K = in_sizes[6];                                  // IN = 4096
    int N = (int)(((long long)in_sizes[1] * 8) / K);      // OUT = 4096
    int M = in_sizes[0] / K;                              // 8192

    float* out = (float*)d_out;

    // Fused prep: convert + dequant in one launch
    {
        int n4 = (M * K) / 4;
        int convBlocks = (n4 + 255) / 256;
        int deqTotal = (K / 8) * N;
        int deqBlocks = (deqTotal + 255) / 256;
        prep_kernel<<<convBlocks + deqBlocks, 256>>>(x, n4, qw, qz, qs, qsz, qss, gix,
                                                     K, N, convBlocks);
    }
    // GEMM
    {
        cudaFuncSetAttribute(gemm_kernel,
                             cudaFuncAttributeMaxDynamicSharedMemorySize, SMEM_DYN);
        dim3 grid(N / BN, M / BM);   // (16, 64)
        gemm_kernel<<<grid, 256, SMEM_DYN>>>(out, M, N, K);
    }
}

// round 7
// speedup vs baseline: 1.0072x; 1.0072x over previous
#include <cuda_runtime.h>
#include <cuda_fp16.h>
#include <cstdint>

// Fixed problem shape: B=4, S=2048 -> M=8192, K=IN=4096, N=OUT=4096, group=32
#define IN_MAX  4096
#define OUT_MAX 4096
#define M_MAX   8192

// Static device scratch (allocation-free per harness rules)
__device__ __half g_X[(size_t)M_MAX * IN_MAX];     // x in fp16, [M][K]
__device__ __half g_WT[(size_t)OUT_MAX * IN_MAX];  // dequantized W^T, [N][K] K-major

// ============================================================================
// PTX helpers
// ============================================================================
__device__ __forceinline__ uint32_t smem_to_u32(const void* p) {
    uint32_t a;
    asm("{ .reg .u64 t; cvta.to.shared.u64 t, %1; cvt.u32.u64 %0, t; }" : "=r"(a) : "l"(p));
    return a;
}
__device__ __forceinline__ void cp_async16(uint32_t dst, const void* src) {
    asm volatile("cp.async.cg.shared.global [%0], [%1], 16;" :: "r"(dst), "l"(src));
}
__device__ __forceinline__ void cp_async_commit() {
    asm volatile("cp.async.commit_group;" ::: "memory");
}
template <int N>
__device__ __forceinline__ void cp_async_wait() {
    asm volatile("cp.async.wait_group %0;" :: "n"(N) : "memory");
}
__device__ __forceinline__ void ldsm4(uint32_t (&r)[4], uint32_t addr) {
    asm volatile("ldmatrix.sync.aligned.m8n8.x4.shared.b16 {%0,%1,%2,%3}, [%4];"
                 : "=r"(r[0]), "=r"(r[1]), "=r"(r[2]), "=r"(r[3]) : "r"(addr));
}
__device__ __forceinline__ void mma16816(float (&c)[4],
                                         uint32_t a0, uint32_t a1, uint32_t a2, uint32_t a3,
                                         uint32_t b0, uint32_t b1) {
    asm volatile("mma.sync.aligned.m16n8k16.row.col.f32.f16.f16.f32 "
                 "{%0,%1,%2,%3}, {%4,%5,%6,%7}, {%8,%9}, {%0,%1,%2,%3};"
                 : "+f"(c[0]), "+f"(c[1]), "+f"(c[2]), "+f"(c[3])
                 : "r"(a0), "r"(a1), "r"(a2), "r"(a3), "r"(b0), "r"(b1));
}

// ============================================================================
// Fused prep kernel: block-range dispatch
//   blocks [0, convBlocks):   x fp32 -> fp16
//   blocks [convBlocks, ...): dequant 4-bit -> fp16 W^T [N][K]
// ============================================================================
__global__ void prep_kernel(const float* __restrict__ x, int n4,
                            const int* __restrict__ qweight,
                            const int* __restrict__ qzeros,
                            const int* __restrict__ qscales,
                            const float* __restrict__ qscales_zeros,
                            const float* __restrict__ qscales_scales,
                            const int* __restrict__ g_idx,
                            int K, int N, int convBlocks) {
    if ((int)blockIdx.x < convBlocks) {
        int i = blockIdx.x * blockDim.x + threadIdx.x;
        if (i < n4) {
            float4 v = reinterpret_cast<const float4*>(x)[i];
            __half2 a = __floats2half2_rn(v.x, v.y);
            __half2 b = __floats2half2_rn(v.z, v.w);
            __half2* o = reinterpret_cast<__half2*>(g_X) + 2 * (size_t)i;
            o[0] = a;
            o[1] = b;
        }
    } else {
        int idx = (blockIdx.x - convBlocks) * blockDim.x + threadIdx.x;
        int P = K >> 3;
        if (idx >= P * N) return;
        int p = idx / N;
        int j = idx - p * N;

        // 8 consecutive K rows (p*8..p*8+7) lie in one group (8 | 32)
        int g = g_idx[p * 8];
        int z = (int)(((unsigned)qzeros[g * (N >> 3) + (j >> 3)] >> ((j & 7) * 4)) & 15u) + 1;
        float sc = ((float)qscales[(size_t)g * N + j] - qscales_zeros[g]) * qscales_scales[g];

        unsigned w = (unsigned)qweight[idx];
        __half h[8];
#pragma unroll
        for (int r = 0; r < 8; r++) {
            int wn = (int)((w >> (4 * r)) & 15u);
            h[r] = __float2half_rn((float)(wn - z) * sc);
        }
        *reinterpret_cast<int4*>(&g_WT[(size_t)j * K + p * 8]) = *reinterpret_cast<int4*>(h);
    }
}

// ============================================================================
// GEMM: mma.sync.m16n8k16 + ldmatrix
//   C[M][N] = g_X[M][K] * g_WT[N][K]^T,  fp16 in / fp32 accum
// CTA tile 128x128x64, 8 warps (2x4), warp tile 64x32,
// 3-stage cp.async pipeline (108KB smem) -> 2 CTAs/SM (16 warps, 4/SMSP).
// 144B row stride: 8-row LDSM phases hit banks {0,4,...,28} — conflict-free.
// ============================================================================
#define BM 128
#define BN 128
#define BK 64
#define STAGES 3
#define LDA (BK + 8)          // 72 halves = 144 bytes
#define LDB (BK + 8)

static constexpr int A_ST = BM * LDA * 2;          // 18432 B per stage
static constexpr int B_ST = BN * LDB * 2;          // 18432 B per stage
static constexpr int OFF_B = STAGES * A_ST;        // 55296
static constexpr int SMEM_DYN = OFF_B + STAGES * B_ST + 16;  // ~108KB

__device__ __forceinline__ void load_stage(uint32_t sbase, int stage,
                                           const __half* Abase, const __half* Bbase,
                                           int k0, int K, int tid, bool active) {
    if (active) {
        uint32_t aoff = sbase + stage * A_ST;
        uint32_t boff = sbase + OFF_B + stage * B_ST;
        // A: 128 rows x 8 chunks (16B) = 1024 -> 4/thread
#pragma unroll
        for (int c = 0; c < 4; c++) {
            int i = tid + c * 256;
            int row = i >> 3;
            int cc = i & 7;
            cp_async16(aoff + row * (LDA * 2) + cc * 16,
                       (const char*)(Abase + (size_t)row * K + k0) + cc * 16);
        }
        // B: 128 rows x 8 chunks = 1024 -> 4/thread
#pragma unroll
        for (int c = 0; c < 4; c++) {
            int i = tid + c * 256;
            int row = i >> 3;
            int cc = i & 7;
            cp_async16(boff + row * (LDB * 2) + cc * 16,
                       (const char*)(Bbase + (size_t)row * K + k0) + cc * 16);
        }
    }
    cp_async_commit();
}

__global__ void __launch_bounds__(256, 2)
gemm_kernel(float* __restrict__ C, int M, int N, int K) {
    extern __shared__ char dsm[];
    uint32_t sbase = smem_to_u32(dsm);

    int tid  = threadIdx.x;
    int lane = tid & 31;
    int warp = tid >> 5;
    int wm   = warp & 1;      // 0..1 -> 64-row slab
    int wn   = warp >> 1;     // 0..3 -> 32-col slab

    int bm = blockIdx.y * BM;
    int bn = blockIdx.x * BN;

    const __half* Abase = &g_X[(size_t)bm * K];
    const __half* Bbase = &g_WT[(size_t)bn * K];

    // ldmatrix byte offsets (within a stage) for this lane
    uint32_t aoff[4], boff[2];
#pragma unroll
    for (int mi = 0; mi < 4; mi++)
        aoff[mi] = (uint32_t)(wm * 64 + mi * 16 + (lane & 15)) * (LDA * 2) + (lane >> 4) * 16;
#pragma unroll
    for (int nb = 0; nb < 2; nb++)
        boff[nb] = (uint32_t)(wn * 32 + nb * 16 + (lane & 15)) * (LDB * 2) + (lane >> 4) * 16;

    float acc[4][4][4];   // [m16][n8][4]
#pragma unroll
    for (int mi = 0; mi < 4; mi++)
#pragma unroll
        for (int nj = 0; nj < 4; nj++)
#pragma unroll
            for (int q = 0; q < 4; q++)
                acc[mi][nj][q] = 0.0f;

    int KT = K / BK;  // 64

#pragma unroll
    for (int s = 0; s < STAGES - 1; s++)
        load_stage(sbase, s, Abase, Bbase, s * BK, K, tid, true);

    for (int kt = 0; kt < KT; kt++) {
        int st = kt % STAGES;
        cp_async_wait<STAGES - 2>();
        __syncthreads();

        load_stage(sbase, (kt + STAGES - 1) % STAGES, Abase, Bbase,
                   (kt + STAGES - 1) * BK, K, tid, (kt + STAGES - 1) < KT);

        uint32_t As = sbase + st * A_ST;
        uint32_t Bs = sbase + OFF_B + st * B_ST;

#pragma unroll
        for (int kk = 0; kk < BK / 16; kk++) {
            uint32_t ko = (uint32_t)kk * 32;   // 16 halves = 32 bytes
            uint32_t RA[4][4];
            uint32_t RB[2][4];
#pragma unroll
            for (int mi = 0; mi < 4; mi++) ldsm4(RA[mi], As + aoff[mi] + ko);
#pragma unroll
            for (int nb = 0; nb < 2; nb++) ldsm4(RB[nb], Bs + boff[nb] + ko);
#pragma unroll
            for (int mi = 0; mi < 4; mi++) {
#pragma unroll
                for (int nj = 0; nj < 4; nj++) {
                    int nb = nj >> 1;
                    int h  = nj & 1;
                    mma16816(acc[mi][nj],
                             RA[mi][0], RA[mi][1], RA[mi][2], RA[mi][3],
                             RB[nb][h], RB[nb][2 + h]);
                }
            }
        }
    }

    // Epilogue: per-thread float2 stores
    int r0 = bm + wm * 64 + (lane >> 2);
    int c0 = bn + wn * 32 + 2 * (lane & 3);
#pragma unroll
    for (int mi = 0; mi < 4; mi++) {
#pragma unroll
        for (int nj = 0; nj < 4; nj++) {
            float* p0 = &C[(size_t)(r0 + mi * 16) * N + c0 + nj * 8];
            float* p1 = &C[(size_t)(r0 + mi * 16 + 8) * N + c0 + nj * 8];
            *reinterpret_cast<float2*>(p0) = make_float2(acc[mi][nj][0], acc[mi][nj][1]);
            *reinterpret_cast<float2*>(p1) = make_float2(acc[mi][nj][2], acc[mi][nj][3]);
        }
    }
}

// ============================================================================
// Launch
// ============================================================================
extern "C" void kernel_launch(void* const* d_in, const int* in_sizes, int n_in,
                              void* d_out, int out_size) {
    const float* x   = (const float*)d_in[0];
    const int*   qw  = (const int*)d_in[1];
    const int*   qz  = (const int*)d_in[2];
    const int*   qs  = (const int*)d_in[3];
    const float* qsz = (const float*)d_in[4];
    const float* qss = (const float*)d_in[5];
    const int*   gix = (const int*)d_in[6];

    int K = in_sizes[6];                                  // IN = 4096
    int N = (int)(((long long)in_sizes[1] * 8) / K);      // OUT = 4096
    int M = in_sizes[0] / K;                              // 8192

    float* out = (float*)d_out;

    // Fused prep: convert + dequant in one launch
    {
        int n4 = (M * K) / 4;
        int convBlocks = (n4 + 255) / 256;
        int deqTotal = (K / 8) * N;
        int deqBlocks = (deqTotal + 255) / 256;
        prep_kernel<<<convBlocks + deqBlocks, 256>>>(x, n4, qw, qz, qs, qsz, qss, gix,
                                                     K, N, convBlocks);
    }
    // GEMM
    {
        cudaFuncSetAttribute(gemm_kernel,
                             cudaFuncAttributeMaxDynamicSharedMemorySize, SMEM_DYN);
        dim3 grid(N / BN, M / BM);   // (32, 64)
        gemm_kernel<<<grid, 256, SMEM_DYN>>>(out, M, N, K);
    }
}